// round 9
// baseline (speedup 1.0000x reference)
#include <cuda_runtime.h>
#include <cuda_bf16.h>
#include <cuda_fp16.h>
#include <math.h>
#include <stdint.h>

#define BATCH 64
#define CIN   640
#define P1    784
#define P2    196
#define NQ    (BATCH * P1)   // 50176
#define NKV   (BATCH * P2)   // 12544
#define INNER 512
#define NHEAD 8
#define DHEAD 64

// GEMM tiling: K-chunk 32, tile rows 128, row stride 40 bf16 (80B)
#define KC        32
#define RSTRIDE   40
#define TILE_B    (128 * RSTRIDE * 2)   // 10240 bytes per tile
#define STAGE_B   (4 * TILE_B)          // 40960 bytes per stage
#define NCHUNK    (CIN / KC)            // 20

// ---------------- scratch ----------------
__device__ __nv_bfloat16  g_hiq [NQ * CIN];
__device__ __nv_bfloat16  g_loq [NQ * CIN];
__device__ __nv_bfloat16  g_hikv[NKV * CIN];
__device__ __nv_bfloat16  g_lokv[NKV * CIN];
__device__ __nv_bfloat16  g_hix [NQ * CIN];
__device__ __nv_bfloat16  g_lox [NQ * CIN];
__device__ __nv_bfloat16  g_hwq [INNER * CIN];
__device__ __nv_bfloat16  g_lwq [INNER * CIN];
__device__ __nv_bfloat16  g_hwkv[2 * INNER * CIN];
__device__ __nv_bfloat16  g_lwkv[2 * INNER * CIN];
__device__ __nv_bfloat16  g_hwds[128 * CIN];
__device__ __nv_bfloat16  g_lwds[128 * CIN];
__device__ float          g_q   [NQ * INNER];
__device__ float          g_kv  [NKV * 2 * INNER];
__device__ float          g_res [NQ * DHEAD];

// =================== helpers ===================
__device__ __forceinline__ uint32_t smem_u32(const void* p) {
    uint32_t a;
    asm("{ .reg .u64 t; cvta.to.shared.u64 t, %1; cvt.u32.u64 %0, t; }" : "=r"(a) : "l"(p));
    return a;
}
#define CP_ASYNC16(sa, ga) \
    asm volatile("cp.async.cg.shared.global [%0], [%1], 16;" :: "r"(sa), "l"(ga))
#define CP_COMMIT() asm volatile("cp.async.commit_group;")
#define CP_WAIT(n)  asm volatile("cp.async.wait_group %0;" :: "n"(n))

#define LDMX4(r, addr) \
    asm volatile("ldmatrix.sync.aligned.m8n8.x4.shared.b16 {%0,%1,%2,%3}, [%4];" \
        : "=r"((r)[0]), "=r"((r)[1]), "=r"((r)[2]), "=r"((r)[3]) : "r"(addr))
#define LDMX2(r, addr) \
    asm volatile("ldmatrix.sync.aligned.m8n8.x2.shared.b16 {%0,%1}, [%2];" \
        : "=r"((r)[0]), "=r"((r)[1]) : "r"(addr))
#define MMA_BF16(c, a, bb_) \
    asm volatile("mma.sync.aligned.m16n8k16.row.col.f32.bf16.bf16.f32 " \
        "{%0,%1,%2,%3}, {%4,%5,%6,%7}, {%8,%9}, {%0,%1,%2,%3};" \
        : "+f"((c)[0]), "+f"((c)[1]), "+f"((c)[2]), "+f"((c)[3]) \
        : "r"((a)[0]), "r"((a)[1]), "r"((a)[2]), "r"((a)[3]), "r"((bb_)[0]), "r"((bb_)[1]))
#define MMA_F16(c, a, bb_) \
    asm volatile("mma.sync.aligned.m16n8k16.row.col.f32.f16.f16.f32 " \
        "{%0,%1,%2,%3}, {%4,%5,%6,%7}, {%8,%9}, {%0,%1,%2,%3};" \
        : "+f"((c)[0]), "+f"((c)[1]), "+f"((c)[2]), "+f"((c)[3]) \
        : "r"((a)[0]), "r"((a)[1]), "r"((a)[2]), "r"((a)[3]), "r"((bb_)[0]), "r"((bb_)[1]))

__device__ __forceinline__ uint32_t pack_bf16(__nv_bfloat16 a, __nv_bfloat16 b) {
    __nv_bfloat162 v;
    v.x = a; v.y = b;
    return *reinterpret_cast<uint32_t*>(&v);
}
__device__ __forceinline__ void split2(float a, float b, uint32_t& hi, uint32_t& lo) {
    __nv_bfloat16 ha = __float2bfloat16(a), hb = __float2bfloat16(b);
    __nv_bfloat16 la = __float2bfloat16(a - __bfloat162float(ha));
    __nv_bfloat16 lb = __float2bfloat16(b - __bfloat162float(hb));
    hi = pack_bf16(ha, hb);
    lo = pack_bf16(la, lb);
}
__device__ __forceinline__ uint32_t packh(float a, float b) {
    __half2 h = __floats2half2_rn(a, b);
    return *reinterpret_cast<uint32_t*>(&h);
}

// ---------------- merged weight split ----------------
#define WQ_N   (INNER * CIN)
#define WKV_N  (2 * INNER * CIN)
#define WDS_N  (128 * CIN)
#define WDS_SRC (64 * CIN)
__global__ void wsplit_all_kernel(const float* __restrict__ wq,
                                  const float* __restrict__ wkv,
                                  const float* __restrict__ wds,
                                  __nv_bfloat16* __restrict__ hwq, __nv_bfloat16* __restrict__ lwq,
                                  __nv_bfloat16* __restrict__ hwkv, __nv_bfloat16* __restrict__ lwkv,
                                  __nv_bfloat16* __restrict__ hwds, __nv_bfloat16* __restrict__ lwds) {
    int i = blockIdx.x * blockDim.x + threadIdx.x;
    float v;
    __nv_bfloat16 *hp, *lp;
    int o;
    if (i < WQ_N) {
        v = wq[i]; hp = hwq; lp = lwq; o = i;
    } else if (i < WQ_N + WKV_N) {
        o = i - WQ_N; v = wkv[o]; hp = hwkv; lp = lwkv;
    } else if (i < WQ_N + WKV_N + WDS_N) {
        o = i - WQ_N - WKV_N;
        v = (o < WDS_SRC) ? wds[o] : 0.f;
        hp = hwds; lp = lwds;
    } else return;
    __nv_bfloat16 h = __float2bfloat16(v);
    hp[o] = h;
    lp[o] = __float2bfloat16(v - __bfloat162float(h));
}

// ---------------- merged prep (compact 1D dispatch) ----------------
#define PREP_Q_BLKS  (64 * 10 * 25)   // 16000
#define PREP_KV_BLKS (64 * 10 * 7)    // 4480
#define PREP_X_BLKS  (64 * 20 * 25)   // 32000
#define PREP_TOTAL   (PREP_Q_BLKS + PREP_KV_BLKS + PREP_X_BLKS)
__global__ void prep_kernel(const float* __restrict__ x,
                            const float* __restrict__ wdwq,
                            const float* __restrict__ qg, const float* __restrict__ qb_,
                            const float* __restrict__ qm, const float* __restrict__ qv,
                            const float* __restrict__ wdwkv,
                            const float* __restrict__ kg, const float* __restrict__ kb_,
                            const float* __restrict__ km, const float* __restrict__ kv_,
                            __nv_bfloat16* __restrict__ hiq, __nv_bfloat16* __restrict__ loq,
                            __nv_bfloat16* __restrict__ hikv, __nv_bfloat16* __restrict__ lokv,
                            __nv_bfloat16* __restrict__ hix, __nv_bfloat16* __restrict__ lox) {
    __shared__ float t[64][33];
    int bid = blockIdx.x;
    int tx = threadIdx.x, ty = threadIdx.y;
    const int H = 28, W = 28;

    if (bid < PREP_Q_BLKS + PREP_KV_BLKS) {
        bool isq = bid < PREP_Q_BLKS;
        int b, c0, p0, P, OW, stride;
        const float *w, *bg, *bbp, *bm, *bv;
        __nv_bfloat16 *hi, *lo;
        if (isq) {
            int r = bid % 250; b = bid / 250;
            c0 = (r / 25) * 64; p0 = (r % 25) * 32;
            P = P1; OW = 28; stride = 1;
            w = wdwq; bg = qg; bbp = qb_; bm = qm; bv = qv; hi = hiq; lo = loq;
        } else {
            int i = bid - PREP_Q_BLKS;
            int r = i % 70; b = i / 70;
            c0 = (r / 7) * 64; p0 = (r % 7) * 32;
            P = P2; OW = 14; stride = 2;
            w = wdwkv; bg = kg; bbp = kb_; bm = km; bv = kv_; hi = hikv; lo = lokv;
        }
        int p = p0 + tx;
        int oy = p / OW, ox = p % OW;
        int iy0 = oy * stride - 1, ix0 = ox * stride - 1;
#pragma unroll
        for (int r = 0; r < 8; r++) {
            int c = c0 + ty + r * 8;
            float val = 0.f;
            if (p < P) {
                const float* xb = x + ((size_t)(b * CIN + c)) * (H * W);
                const float* wc = w + c * 9;
                float acc = 0.f;
#pragma unroll
                for (int dy = 0; dy < 3; dy++) {
                    int iy = iy0 + dy;
                    if (iy < 0 || iy >= H) continue;
#pragma unroll
                    for (int dx = 0; dx < 3; dx++) {
                        int ix = ix0 + dx;
                        if (ix < 0 || ix >= W) continue;
                        acc += xb[iy * W + ix] * wc[dy * 3 + dx];
                    }
                }
                float inv = bg[c] * rsqrtf(bv[c] + 1e-5f);
                val = (acc - bm[c]) * inv + bbp[c];
            }
            t[ty + r * 8][tx] = val;
        }
        __syncthreads();
#pragma unroll
        for (int r = 0; r < 4; r++) {
            int nl = ty + r * 8;
            int pp = p0 + nl;
            if (pp < P) {
                size_t n = (size_t)b * P + pp;
                uint32_t hv, lv;
                split2(t[2 * tx][nl], t[2 * tx + 1][nl], hv, lv);
                *(uint32_t*)(hi + n * CIN + c0 + 2 * tx) = hv;
                *(uint32_t*)(lo + n * CIN + c0 + 2 * tx) = lv;
            }
        }
    } else {
        int i = bid - PREP_Q_BLKS - PREP_KV_BLKS;
        int r = i % 500, b = i / 500;
        int c0 = (r / 25) * 32, p0 = (r % 25) * 32;
#pragma unroll
        for (int rr = 0; rr < 4; rr++) {
            int c = c0 + ty + rr * 8;
            int p = p0 + tx;
            t[ty + rr * 8][tx] = (p < P1) ? x[((size_t)b * CIN + c) * P1 + p] : 0.f;
        }
        __syncthreads();
#pragma unroll
        for (int rr = 0; rr < 4; rr++) {
            int p = p0 + ty + rr * 8;
            int c = c0 + tx;
            if (p < P1) {
                float v = t[tx][ty + rr * 8];
                __nv_bfloat16 h = __float2bfloat16(v);
                size_t o = ((size_t)b * P1 + p) * CIN + c;
                hix[o] = h;
                lox[o] = __float2bfloat16(v - __bfloat162float(h));
            }
        }
    }
}

// ---------------- merged 3-problem mma GEMM (K-chunk 32, 2 CTAs/SM) ----------------
#define GQ_CTAS  (4 * 392)    // 1568
#define GKV_CTAS (8 * 98)     // 784
#define GR_CTAS  392
__global__ void __launch_bounds__(256, 2)
mma_gemm_all(const __nv_bfloat16* __restrict__ hwq,  const __nv_bfloat16* __restrict__ lwq,
             const __nv_bfloat16* __restrict__ hiq,  const __nv_bfloat16* __restrict__ loq,
             float* __restrict__ Yq,
             const __nv_bfloat16* __restrict__ hwkv, const __nv_bfloat16* __restrict__ lwkv,
             const __nv_bfloat16* __restrict__ hikv, const __nv_bfloat16* __restrict__ lokv,
             float* __restrict__ Ykv,
             const __nv_bfloat16* __restrict__ hwds, const __nv_bfloat16* __restrict__ lwds,
             const __nv_bfloat16* __restrict__ hix,  const __nv_bfloat16* __restrict__ lox,
             float* __restrict__ Yr,
             const float* __restrict__ dg, const float* __restrict__ db,
             const float* __restrict__ dm, const float* __restrict__ dv) {
    extern __shared__ __nv_bfloat16 smem[];

    int bx = blockIdx.x;
    const __nv_bfloat16 *hiW, *loW, *hiX, *loX;
    float* Y;
    int CO, m0, n0;
    const float *bg = nullptr, *bb = nullptr, *bm = nullptr, *bv = nullptr;
    if (bx < GQ_CTAS) {
        hiW = hwq; loW = lwq; hiX = hiq; loX = loq; Y = Yq; CO = INNER;
        m0 = (bx & 3) * 128; n0 = (bx >> 2) * 128;
    } else if (bx < GQ_CTAS + GKV_CTAS) {
        int i = bx - GQ_CTAS;
        hiW = hwkv; loW = lwkv; hiX = hikv; loX = lokv; Y = Ykv; CO = 2 * INNER;
        m0 = (i & 7) * 128; n0 = (i >> 3) * 128;
    } else {
        int i = bx - GQ_CTAS - GKV_CTAS;
        hiW = hwds; loW = lwds; hiX = hix; loX = lox; Y = Yr; CO = DHEAD;
        m0 = 0; n0 = i * 128;
        bg = dg; bb = db; bm = dm; bv = dv;
    }

    int tid = threadIdx.x, lane = tid & 31, wid = tid >> 5;
    int warp_m = wid >> 2, warp_n = wid & 3;
    int lrow = tid >> 1, lhalf = tid & 1;

    float acc[4][4][4];
#pragma unroll
    for (int i = 0; i < 4; i++)
#pragma unroll
        for (int j = 0; j < 4; j++)
#pragma unroll
            for (int k = 0; k < 4; k++) acc[i][j][k] = 0.f;

    int a_row = warp_m * 64 + ((lane & 7) | (((lane >> 3) & 1) << 3));
    int a_off = a_row * (RSTRIDE * 2) + (lane >> 4) * 16;
    int b_row = warp_n * 32 + (lane & 7);
    int b_off = b_row * (RSTRIDE * 2) + ((lane >> 3) & 1) * 16;

#define LOADC(ch, buf) do { \
        int _kk = (ch) * KC; \
        const __nv_bfloat16* _p0 = hiW + (size_t)(m0 + lrow) * CIN + _kk + lhalf * 16; \
        const __nv_bfloat16* _p1 = loW + (size_t)(m0 + lrow) * CIN + _kk + lhalf * 16; \
        const __nv_bfloat16* _p2 = hiX + (size_t)(n0 + lrow) * CIN + _kk + lhalf * 16; \
        const __nv_bfloat16* _p3 = loX + (size_t)(n0 + lrow) * CIN + _kk + lhalf * 16; \
        uint32_t _b = smem_u32(smem) + (uint32_t)(buf) * (uint32_t)STAGE_B + lrow * 80u + lhalf * 32u; \
        CP_ASYNC16(_b + 0u * TILE_B,      _p0);      CP_ASYNC16(_b + 0u * TILE_B + 16, _p0 + 8); \
        CP_ASYNC16(_b + 1u * TILE_B,      _p1);      CP_ASYNC16(_b + 1u * TILE_B + 16, _p1 + 8); \
        CP_ASYNC16(_b + 2u * TILE_B,      _p2);      CP_ASYNC16(_b + 2u * TILE_B + 16, _p2 + 8); \
        CP_ASYNC16(_b + 3u * TILE_B,      _p3);      CP_ASYNC16(_b + 3u * TILE_B + 16, _p3 + 8); \
        CP_COMMIT(); \
    } while (0)

    LOADC(0, 0);

    for (int s = 0; s < NCHUNK; s++) {
        int buf = s & 1;
        if (s + 1 < NCHUNK) {
            LOADC(s + 1, buf ^ 1);
            CP_WAIT(1);
        } else {
            CP_WAIT(0);
        }
        __syncthreads();

        uint32_t base = smem_u32(smem) + (uint32_t)buf * (uint32_t)STAGE_B;
        uint32_t hiAo = base + a_off;
        uint32_t loAo = base + TILE_B + a_off;
        uint32_t hiBo = base + 2u * TILE_B + b_off;
        uint32_t loBo = base + 3u * TILE_B + b_off;
#pragma unroll
        for (int ks = 0; ks < 2; ks++) {
            uint32_t ah[4][4], al[4][4], bh2[4][2], bl2[4][2];
#pragma unroll
            for (int mt = 0; mt < 4; mt++) {
                uint32_t off = mt * 16 * (RSTRIDE * 2) + ks * 32;
                LDMX4(ah[mt], hiAo + off);
                LDMX4(al[mt], loAo + off);
            }
#pragma unroll
            for (int nt = 0; nt < 4; nt++) {
                uint32_t off = nt * 8 * (RSTRIDE * 2) + ks * 32;
                LDMX2(bh2[nt], hiBo + off);
                LDMX2(bl2[nt], loBo + off);
            }
#pragma unroll
            for (int mt = 0; mt < 4; mt++)
#pragma unroll
                for (int nt = 0; nt < 4; nt++) {
                    MMA_BF16(acc[mt][nt], ah[mt], bh2[nt]);
                    MMA_BF16(acc[mt][nt], al[mt], bh2[nt]);
                    MMA_BF16(acc[mt][nt], ah[mt], bl2[nt]);
                }
        }
        __syncthreads();
    }

    // smem-staged coalesced epilogue
    float* st = (float*)smem;     // 128 x 132 floats = 67584 B < 81920
    int g = lane >> 2, t4 = lane & 3;
#pragma unroll
    for (int mt = 0; mt < 4; mt++) {
        int mAl = warp_m * 64 + mt * 16 + g;
        int mBl = mAl + 8;
        int mA = m0 + mAl, mB = m0 + mBl;
        float sA = 1.f, hA = 0.f, sB = 1.f, hB = 0.f;
        if (bg) {
            if (mA < CO) { float iv = bg[mA] * rsqrtf(bv[mA] + 1e-5f); sA = iv; hA = bb[mA] - bm[mA] * iv; }
            if (mB < CO) { float iv = bg[mB] * rsqrtf(bv[mB] + 1e-5f); sB = iv; hB = bb[mB] - bm[mB] * iv; }
        }
#pragma unroll
        for (int nt = 0; nt < 4; nt++) {
            int nl = warp_n * 32 + nt * 8 + 2 * t4;
            st[nl * 132 + mAl]       = acc[mt][nt][0] * sA + hA;
            st[(nl + 1) * 132 + mAl] = acc[mt][nt][1] * sA + hA;
            st[nl * 132 + mBl]       = acc[mt][nt][2] * sB + hB;
            st[(nl + 1) * 132 + mBl] = acc[mt][nt][3] * sB + hB;
        }
    }
    __syncthreads();
    int row = tid >> 1, half = tid & 1;
    int cmax = CO - m0; if (cmax > 128) cmax = 128;
    int cstart = half * (cmax >> 1), cend = cstart + (cmax >> 1);
    float* dst = Y + (size_t)(n0 + row) * CO + m0;
    for (int col = cstart; col < cend; col += 4)
        *(float4*)(dst + col) = *(float4*)(st + row * 132 + col);
#undef LOADC
}

// ---------------- tensor-core attention + residual + LN + mean-pool ----------------
// one CTA per (b,h); 8 warps; each warp processes 16-query strips.
// smem: KHI[200][72] bf16, KLO[200][72] bf16, VT[64][216] fp16, QS per warp, SR[8][64] f32
#define KROWS   200
#define KSTR    72
#define VSTR    216
#define QS_ELE  (16 * KSTR)           // per warp per half
#define SM_KHI  0
#define SM_KLO  (KROWS * KSTR)
#define SM_VT   (2 * KROWS * KSTR)
#define SM_QS   (SM_VT + 64 * VSTR)
#define SM_BF16_TOT (SM_QS + 8 * 2 * QS_ELE)
#define ATTN_SMEM_B (SM_BF16_TOT * 2 + 8 * 64 * 4)

__global__ void __launch_bounds__(256, 1)
attn_mma_kernel(const float* __restrict__ qbuf,   // [n][512]
                const float* __restrict__ kvbuf,  // [n2][1024]
                const float* __restrict__ resb,   // [n][64]
                const float* __restrict__ lng, const float* __restrict__ lnb,
                float* __restrict__ out) {
    extern __shared__ __nv_bfloat16 sb[];
    __nv_bfloat16* KHI = sb + SM_KHI;
    __nv_bfloat16* KLO = sb + SM_KLO;
    __half*        VT  = (__half*)(sb + SM_VT);
    __nv_bfloat16* QSB = sb + SM_QS;
    float* SR = (float*)(sb + SM_BF16_TOT);   // [8][64]

    int bh = blockIdx.x;
    int b = bh >> 3, h = bh & 7;
    int tid = threadIdx.x, lane = tid & 31, wid = tid >> 5;
    int g = lane >> 2, t4 = lane & 3;

    // ---- load K hi/lo (rows 196..199 zeroed) ----
    const float* kvbase = kvbuf + (size_t)b * P2 * 1024 + h * 64;
    {
        int r = tid >> 1, hf = tid & 1;
#pragma unroll
        for (int j0 = 0; j0 < KROWS; j0 += 128) {
            int j = j0 + r;
            if (j < KROWS) {
                __nv_bfloat16* kh = KHI + j * KSTR + hf * 32;
                __nv_bfloat16* kl = KLO + j * KSTR + hf * 32;
                if (j < P2) {
                    const float4* src = (const float4*)(kvbase + (size_t)j * 1024 + hf * 32);
#pragma unroll
                    for (int k = 0; k < 8; k++) {
                        float4 v = src[k];
                        uint32_t h0, l0, h1, l1;
                        split2(v.x, v.y, h0, l0);
                        split2(v.z, v.w, h1, l1);
                        *(uint32_t*)(kh + k * 4)     = h0;
                        *(uint32_t*)(kh + k * 4 + 2) = h1;
                        *(uint32_t*)(kl + k * 4)     = l0;
                        *(uint32_t*)(kl + k * 4 + 2) = l1;
                    }
                } else {
#pragma unroll
                    for (int k = 0; k < 16; k++) {
                        *(uint32_t*)(kh + k * 2) = 0u;
                        *(uint32_t*)(kl + k * 2) = 0u;
                    }
                }
            }
        }
    }
    // ---- load V transposed (fp16); cols 196..207 zeroed ----
    {
        if (tid < P2) {
            const float* vsrc = kvbase + (size_t)tid * 1024 + 512;
#pragma unroll
            for (int d = 0; d < 64; d++)
                VT[d * VSTR + tid] = __float2half(vsrc[d]);
        } else if (tid < 208) {
#pragma unroll
            for (int d = 0; d < 64; d++)
                VT[d * VSTR + tid] = __float2half(0.f);
        }
    }
    __syncthreads();

    __nv_bfloat16* qhi = QSB + wid * 2 * QS_ELE;
    __nv_bfloat16* qlo = qhi + QS_ELE;
    uint32_t khiA = smem_u32(KHI), kloA = smem_u32(KLO), vtA = smem_u32(VT);
    uint32_t qhiA = smem_u32(qhi), qloA = smem_u32(qlo);

    uint32_t a_off = (((lane & 7) | (((lane >> 3) & 1) << 3)) * KSTR * 2) + (lane >> 4) * 16;
    uint32_t b_off = ((lane & 7) * KSTR * 2) + ((lane >> 3) & 1) * 16;
    uint32_t v_off = ((lane & 7) * VSTR * 2) + ((lane >> 3) & 1) * 16;

    float zacc[8][2];
#pragma unroll
    for (int i = 0; i < 8; i++) { zacc[i][0] = 0.f; zacc[i][1] = 0.f; }

    const size_t nb = (size_t)b * P1;

    for (int s = wid; s < 49; s += 8) {
        int i0 = s * 16;
        __syncwarp();
        // ---- stage Q strip (16 rows) hi/lo ----
        {
            int r = lane >> 1, hf = lane & 1;
            const float4* src = (const float4*)(qbuf + (nb + i0 + r) * INNER + h * 64 + hf * 32);
            __nv_bfloat16* qh = qhi + r * KSTR + hf * 32;
            __nv_bfloat16* ql = qlo + r * KSTR + hf * 32;
#pragma unroll
            for (int k = 0; k < 8; k++) {
                float4 v = src[k];
                uint32_t h0, l0, h1, l1;
                split2(v.x, v.y, h0, l0);
                split2(v.z, v.w, h1, l1);
                *(uint32_t*)(qh + k * 4)     = h0;
                *(uint32_t*)(qh + k * 4 + 2) = h1;
                *(uint32_t*)(ql + k * 4)     = l0;
                *(uint32_t*)(ql + k * 4 + 2) = l1;
            }
        }
        __syncwarp();

        // ---- A fragments for Q (4 k-blocks of 16) ----
        uint32_t ah[4][4], al[4][4];
#pragma unroll
        for (int kb = 0; kb < 4; kb++) {
            LDMX4(ah[kb], qhiA + a_off + kb * 32);
            LDMX4(al[kb], qloA + a_off + kb * 32);
        }

        // ---- QK^T: S[16][200] in 25 n-tiles ----
        float e[25][4];
#pragma unroll
        for (int nt = 0; nt < 25; nt++) {
            float c[4] = {0.f, 0.f, 0.f, 0.f};
            uint32_t roff = nt * 8 * (KSTR * 2);
#pragma unroll
            for (int kb = 0; kb < 4; kb++) {
                uint32_t bhf[2], blf[2];
                LDMX2(bhf, khiA + roff + b_off + kb * 32);
                LDMX2(blf, kloA + roff + b_off + kb * 32);
                MMA_BF16(c, ah[kb], bhf);
                MMA_BF16(c, al[kb], bhf);
                MMA_BF16(c, ah[kb], blf);
            }
            e[nt][0] = c[0]; e[nt][1] = c[1]; e[nt][2] = c[2]; e[nt][3] = c[3];
        }

        // ---- softmax (rows g and g+8) ----
#pragma unroll
        for (int nt = 0; nt < 25; nt++)
#pragma unroll
            for (int k = 0; k < 4; k++) e[nt][k] *= 0.125f;
        if (t4 >= 2) { e[24][0] = -1e30f; e[24][1] = -1e30f; e[24][2] = -1e30f; e[24][3] = -1e30f; }
        float mx0 = -1e30f, mx1 = -1e30f;
#pragma unroll
        for (int nt = 0; nt < 25; nt++) {
            mx0 = fmaxf(mx0, fmaxf(e[nt][0], e[nt][1]));
            mx1 = fmaxf(mx1, fmaxf(e[nt][2], e[nt][3]));
        }
        mx0 = fmaxf(mx0, __shfl_xor_sync(0xffffffffu, mx0, 1));
        mx0 = fmaxf(mx0, __shfl_xor_sync(0xffffffffu, mx0, 2));
        mx1 = fmaxf(mx1, __shfl_xor_sync(0xffffffffu, mx1, 1));
        mx1 = fmaxf(mx1, __shfl_xor_sync(0xffffffffu, mx1, 2));
        float sm0 = 0.f, sm1 = 0.f;
#pragma unroll
        for (int nt = 0; nt < 25; nt++) {
            e[nt][0] = __expf(e[nt][0] - mx0);
            e[nt][1] = __expf(e[nt][1] - mx0);
            e[nt][2] = __expf(e[nt][2] - mx1);
            e[nt][3] = __expf(e[nt][3] - mx1);
            sm0 += e[nt][0] + e[nt][1];
            sm1 += e[nt][2] + e[nt][3];
        }
        sm0 += __shfl_xor_sync(0xffffffffu, sm0, 1);
        sm0 += __shfl_xor_sync(0xffffffffu, sm0, 2);
        sm1 += __shfl_xor_sync(0xffffffffu, sm1, 1);
        sm1 += __shfl_xor_sync(0xffffffffu, sm1, 2);
        float inv0 = 1.f / sm0, inv1 = 1.f / sm1;

        // ---- P @ V : single-pass fp16 (P fp16, V fp16) ----
        float co[8][4];
#pragma unroll
        for (int i = 0; i < 8; i++) { co[i][0] = 0.f; co[i][1] = 0.f; co[i][2] = 0.f; co[i][3] = 0.f; }
#pragma unroll
        for (int kb2 = 0; kb2 < 13; kb2++) {
            int tA = 2 * kb2, tB = 2 * kb2 + 1;
            uint32_t p2[4];
            p2[0] = packh(e[tA][0], e[tA][1]);
            p2[1] = packh(e[tA][2], e[tA][3]);
            if (tB < 25) {
                p2[2] = packh(e[tB][0], e[tB][1]);
                p2[3] = packh(e[tB][2], e[tB][3]);
            } else {
                p2[2] = 0u; p2[3] = 0u;
            }
#pragma unroll
            for (int ntv = 0; ntv < 8; ntv++) {
                uint32_t bv2[2];
                LDMX2(bv2, vtA + ntv * 8 * (VSTR * 2) + v_off + kb2 * 32);
                MMA_F16(co[ntv], p2, bv2);
            }
        }

        // ---- normalize + residual + per-row LN stats ----
        int row0 = i0 + g, row1 = row0 + 8;
        const float* r0p = resb + (nb + row0) * 64;
        const float* r1p = resb + (nb + row1) * 64;
        float s10 = 0.f, s20 = 0.f, s11 = 0.f, s21 = 0.f;
#pragma unroll
        for (int ntv = 0; ntv < 8; ntv++) {
            int d = ntv * 8 + 2 * t4;
            float2 rv0 = *(const float2*)(r0p + d);
            float2 rv1 = *(const float2*)(r1p + d);
            float a0 = co[ntv][0] * inv0 + rv0.x;
            float a1 = co[ntv][1] * inv0 + rv0.y;
            float b0 = co[ntv][2] * inv1 + rv1.x;
            float b1 = co[ntv][3] * inv1 + rv1.y;
            co[ntv][0] = a0; co[ntv][1] = a1; co[ntv][2] = b0; co[ntv][3] = b1;
            s10 += a0 + a1; s20 += a0 * a0 + a1 * a1;
            s11 += b0 + b1; s21 += b0 * b0 + b1 * b1;
        }
        s10 += __shfl_xor_sync(0xffffffffu, s10, 1);
        s10 += __shfl_xor_sync(0xffffffffu, s10, 2);
        s20 += __shfl_xor_sync(0xffffffffu, s20, 1);
        s20 += __shfl_xor_sync(0xffffffffu, s20, 2);
        s11 += __shfl_xor_sync(0xffffffffu, s11, 1);
        s11 += __shfl_xor_sync(0xffffffffu, s11, 2);
        s21 += __shfl_xor_sync(0xffffffffu, s21, 1);
        s21 += __shfl_xor_sync(0xffffffffu, s21, 2);
        float mean0 = s10 * (1.f / 64.f);
        float var0  = fmaxf(s20 * (1.f / 64.f) - mean0 * mean0, 0.f);
        float istd0 = 1.f / (sqrtf(var0) + 1e-5f);
        float mean1 = s11 * (1.f / 64.f);
        float var1  = fmaxf(s21 * (1.f / 64.f) - mean1 * mean1, 0.f);
        float istd1 = 1.f / (sqrtf(var1) + 1e-5f);
#pragma unroll
        for (int ntv = 0; ntv < 8; ntv++) {
            zacc[ntv][0] += (co[ntv][0] - mean0) * istd0 + (co[ntv][2] - mean1) * istd1;
            zacc[ntv][1] += (co[ntv][1] - mean0) * istd0 + (co[ntv][3] - mean1) * istd1;
        }
    }

    // ---- reduce zacc across g (lanes differing in bits 2..4), then across warps ----
#pragma unroll
    for (int ntv = 0; ntv < 8; ntv++) {
#pragma unroll
        for (int off = 4; off <= 16; off <<= 1) {
            zacc[ntv][0] += __shfl_xor_sync(0xffffffffu, zacc[ntv][0], off);
            zacc[ntv][1] += __shfl_xor_sync(0xffffffffu, zacc[ntv][1], off);
        }
    }
    if (g == 0) {
#pragma unroll
        for (int ntv = 0; ntv < 8; ntv++) {
            SR[wid * 64 + ntv * 8 + 2 * t4]     = zacc[ntv][0];
            SR[wid * 64 + ntv * 8 + 2 * t4 + 1] = zacc[ntv][1];
        }
    }
    __syncthreads();
    if (tid < 64) {
        float sum = 0.f;
#pragma unroll
        for (int w = 0; w < 8; w++) sum += SR[w * 64 + tid];
        out[(size_t)bh * 64 + tid] = sum * (1.f / 784.f) * lng[h * 64 + tid] + lnb[h * 64 + tid];
    }
}

// ---------------- launch ----------------
extern "C" void kernel_launch(void* const* d_in, const int* in_sizes, int n_in,
                              void* d_out, int out_size) {
    (void)in_sizes; (void)n_in; (void)out_size;
    const float* x      = (const float*)d_in[0];
    const float* w_dwq  = (const float*)d_in[1];
    const float* w_pwq  = (const float*)d_in[2];
    const float* w_dwkv = (const float*)d_in[3];
    const float* w_pwkv = (const float*)d_in[4];
    const float* w_ds   = (const float*)d_in[5];
    const float* ln_g   = (const float*)d_in[6];
    const float* ln_b   = (const float*)d_in[7];
    const float* bnq_g  = (const float*)d_in[8];
    const float* bnq_b  = (const float*)d_in[9];
    const float* bnq_m  = (const float*)d_in[10];
    const float* bnq_v  = (const float*)d_in[11];
    const float* bnkv_g = (const float*)d_in[12];
    const float* bnkv_b = (const float*)d_in[13];
    const float* bnkv_m = (const float*)d_in[14];
    const float* bnkv_v = (const float*)d_in[15];
    const float* bnds_g = (const float*)d_in[16];
    const float* bnds_b = (const float*)d_in[17];
    const float* bnds_m = (const float*)d_in[18];
    const float* bnds_v = (const float*)d_in[19];
    float* out = (float*)d_out;

    float *qbuf, *kvbuf, *resb;
    __nv_bfloat16 *hiq, *loq, *hikv, *lokv, *hix, *lox;
    __nv_bfloat16 *hwq, *lwq, *hwkv, *lwkv, *hwds, *lwds;
    cudaGetSymbolAddress((void**)&hiq,  g_hiq);
    cudaGetSymbolAddress((void**)&loq,  g_loq);
    cudaGetSymbolAddress((void**)&hikv, g_hikv);
    cudaGetSymbolAddress((void**)&lokv, g_lokv);
    cudaGetSymbolAddress((void**)&hix,  g_hix);
    cudaGetSymbolAddress((void**)&lox,  g_lox);
    cudaGetSymbolAddress((void**)&hwq,  g_hwq);
    cudaGetSymbolAddress((void**)&lwq,  g_lwq);
    cudaGetSymbolAddress((void**)&hwkv, g_hwkv);
    cudaGetSymbolAddress((void**)&lwkv, g_lwkv);
    cudaGetSymbolAddress((void**)&hwds, g_hwds);
    cudaGetSymbolAddress((void**)&lwds, g_lwds);
    cudaGetSymbolAddress((void**)&qbuf, g_q);
    cudaGetSymbolAddress((void**)&kvbuf, g_kv);
    cudaGetSymbolAddress((void**)&resb, g_res);

    // #1: weight splits
    {
        int tot = WQ_N + WKV_N + WDS_N;
        wsplit_all_kernel<<<(tot + 255) / 256, 256>>>(w_pwq, w_pwkv, w_ds,
                                                      hwq, lwq, hwkv, lwkv, hwds, lwds);
    }
    // #2: merged prep (compact dispatch)
    prep_kernel<<<PREP_TOTAL, dim3(32, 8)>>>(x,
                                             w_dwq, bnq_g, bnq_b, bnq_m, bnq_v,
                                             w_dwkv, bnkv_g, bnkv_b, bnkv_m, bnkv_v,
                                             hiq, loq, hikv, lokv, hix, lox);
    // #3: merged GEMMs (q + kv + residual)
    {
        size_t gemm_smem = 2 * STAGE_B;   // 81920
        cudaFuncSetAttribute(mma_gemm_all, cudaFuncAttributeMaxDynamicSharedMemorySize, (int)gemm_smem);
        mma_gemm_all<<<GQ_CTAS + GKV_CTAS + GR_CTAS, 256, gemm_smem>>>(
            hwq, lwq, hiq, loq, qbuf,
            hwkv, lwkv, hikv, lokv, kvbuf,
            hwds, lwds, hix, lox, resb,
            bnds_g, bnds_b, bnds_m, bnds_v);
    }
    // #4: tensor-core attention (profiled launch)
    {
        cudaFuncSetAttribute(attn_mma_kernel, cudaFuncAttributeMaxDynamicSharedMemorySize, ATTN_SMEM_B);
        attn_mma_kernel<<<BATCH * NHEAD, 256, ATTN_SMEM_B>>>(qbuf, kvbuf, resb, ln_g, ln_b, out);
    }
}